// round 16
// baseline (speedup 1.0000x reference)
#include <cuda_runtime.h>
#include <cstddef>
#include <cstdint>

// Consolidated champion. 15-round matrix: DRAM% pinned 63-75% across load
// path (LDG/cp.async/TMA), store path, occupancy (21-36%), wavefronts/row
// (192-288), ILP and instruction count => fabric-bound at ~5.9-6.0 TB/s
// effective mixed read/write; ncu durations converged (81.0/81.6/82.8).
// This round keeps the best body (R15: packed f32x2 butterflies, 64-bit
// vectorized transpose rows, register-resident packed scale/shift,
// 16 warps/SM) and tightens the steady state:
//   - #pragma unroll 1 on the persistent loop (regs 114 suggested ptxas
//     unrolled/double-booked the body; tight loop -> fewer regs, smaller
//     I-footprint across 2368 resident warps).
//
// Structure: one warp per row of 1024 floats, persistent grid-stride.
// Thread owns 32 elements i = 128k+4lane+b as v[c], c=4k+b.
// FWHT1024 = FWHT32 over c-bits (i bits 0,1,7,8,9; packed f32x2)
//          o FWHT32 over lane-bits (i bits 2..6) via padded-SMEM transpose.

#define NWARPS 8
#define PAD 34                                   // float2-aligned padding

__device__ __forceinline__ unsigned long long pk2(float lo, float hi)
{
    unsigned long long r;
    asm("mov.b64 %0, {%1, %2};" : "=l"(r) : "f"(lo), "f"(hi));
    return r;
}
__device__ __forceinline__ void upk2(float& lo, float& hi, unsigned long long p)
{
    asm("mov.b64 {%0, %1}, %2;" : "=f"(lo), "=f"(hi) : "l"(p));
}
__device__ __forceinline__ void pbfly(float* v, int i, int j)
{
    unsigned long long A = pk2(v[2*i], v[2*i+1]);
    unsigned long long B = pk2(v[2*j], v[2*j+1]);
    unsigned long long S, D;
    asm("add.rn.f32x2 %0, %1, %2;" : "=l"(S) : "l"(A), "l"(B));
    asm("sub.rn.f32x2 %0, %1, %2;" : "=l"(D) : "l"(A), "l"(B));
    upk2(v[2*i], v[2*i+1], S);
    upk2(v[2*j], v[2*j+1], D);
}
__device__ __forceinline__ void fwht32(float* v)
{
    #pragma unroll
    for (int q = 0; q < 16; q++) {               // stage m=1: scalar
        float u = v[2*q], w = v[2*q+1];
        v[2*q] = u + w;  v[2*q+1] = u - w;
    }
    #pragma unroll
    for (int mq = 1; mq < 16; mq <<= 1) {        // m=2,4,8,16: packed f32x2
        #pragma unroll
        for (int q = 0; q < 16; q++)
            if ((q & mq) == 0) pbfly(v, q, q | mq);
    }
}

__global__ void __launch_bounds__(256, 2)
fwht1024_kernel(const float* __restrict__ x,
                const float* __restrict__ scale,
                const float* __restrict__ shift,
                float* __restrict__ out,
                int nrows, int warp_stride)
{
    __shared__ float xch[NWARPS][32 * PAD];      // 4352 B/warp, 34.8 KB/block
    const int wlocal = threadIdx.x >> 5;
    const int lane   = threadIdx.x & 31;
    float*  __restrict__ sm  = xch[wlocal];
    float2* __restrict__ smv = reinterpret_cast<float2*>(sm + lane * PAD);

    // ---- packed register-resident scale*(1/32) and shift ----
    // column of v[4k+b] is element 128k+4lane+b == float4 idx 32k+lane, comp b
    unsigned long long spp[16], sbp[16];
    {
        const float4* __restrict__ sc4 = reinterpret_cast<const float4*>(scale);
        const float4* __restrict__ sh4 = reinterpret_cast<const float4*>(shift);
        const float inv = 0.03125f;              // 1/sqrt(1024)
        #pragma unroll
        for (int k = 0; k < 8; k++) {
            float4 s4 = __ldg(&sc4[k * 32 + lane]);
            float4 h4 = __ldg(&sh4[k * 32 + lane]);
            spp[2*k+0] = pk2(s4.x * inv, s4.y * inv);
            spp[2*k+1] = pk2(s4.z * inv, s4.w * inv);
            sbp[2*k+0] = pk2(h4.x, h4.y);
            sbp[2*k+1] = pk2(h4.z, h4.w);
        }
    }

    const int wid = blockIdx.x * NWARPS + wlocal;
    const float4* __restrict__ xin =
        reinterpret_cast<const float4*>(x) + (size_t)wid * 256u + lane;
    float4* __restrict__ xo =
        reinterpret_cast<float4*>(out) + (size_t)wid * 256u + lane;
    const size_t step = (size_t)warp_stride * 256u;

    #pragma unroll 1
    for (int row = wid; row < nrows;
         row += warp_stride, xin += step, xo += step) {

        float v[32];

        // ---- coalesced streaming load: float4 index 32k+lane ----
        #pragma unroll
        for (int k = 0; k < 8; k++) {
            float4 t = __ldcs(xin + k * 32);
            v[4*k+0] = t.x; v[4*k+1] = t.y; v[4*k+2] = t.z; v[4*k+3] = t.w;
        }

        // ---- FWHT32 over register index (element bits 0,1,7,8,9) ----
        fwht32(v);

        // ---- transpose: row writes 64-bit (2-phase, bank-clean),
        //                 column reads scalar (banks lane+2j: CF) ----
        #pragma unroll
        for (int q = 0; q < 16; q++)
            smv[q] = make_float2(v[2*q], v[2*q+1]);
        __syncwarp();
        #pragma unroll
        for (int j = 0; j < 32; j++) v[j] = sm[j * PAD + lane];

        // ---- FWHT32 over new register index (element bits 2..6) ----
        fwht32(v);

        // ---- transpose back: column writes scalar (CF),
        //      row reads 64-bit (touches only this thread's words) ----
        #pragma unroll
        for (int j = 0; j < 32; j++) sm[j * PAD + lane] = v[j];
        __syncwarp();
        #pragma unroll
        for (int q = 0; q < 16; q++) {
            float2 t = smv[q];
            v[2*q] = t.x; v[2*q+1] = t.y;
        }

        // ---- epilogue: packed fma.rn.f32x2 scale/shift, streaming store ----
        #pragma unroll
        for (int k = 0; k < 8; k++) {
            unsigned long long a01 = pk2(v[4*k+0], v[4*k+1]);
            unsigned long long a23 = pk2(v[4*k+2], v[4*k+3]);
            unsigned long long r01, r23;
            asm("fma.rn.f32x2 %0, %1, %2, %3;"
                : "=l"(r01) : "l"(a01), "l"(spp[2*k+0]), "l"(sbp[2*k+0]));
            asm("fma.rn.f32x2 %0, %1, %2, %3;"
                : "=l"(r23) : "l"(a23), "l"(spp[2*k+1]), "l"(sbp[2*k+1]));
            float4 r;
            upk2(r.x, r.y, r01);
            upk2(r.z, r.w, r23);
            __stcs(xo + k * 32, r);
        }
        // next-iter transpose writes touch only words this thread last read: safe
    }
}

extern "C" void kernel_launch(void* const* d_in, const int* in_sizes, int n_in,
                              void* d_out, int out_size)
{
    const float* x     = (const float*)d_in[0];
    const float* scale = (const float*)d_in[1];
    const float* shift = (const float*)d_in[2];
    float* out = (float*)d_out;

    const int nrows = in_sizes[0] / 1024;

    int sms = 148;
    cudaDeviceGetAttribute(&sms, cudaDevAttrMultiProcessorCount, 0);
    const int blocks = sms * 2;                 // 2 CTAs/SM, 16 warps/SM
    const int warp_stride = blocks * NWARPS;    // persistent grid-stride

    fwht1024_kernel<<<blocks, 32 * NWARPS>>>(x, scale, shift, out,
                                             nrows, warp_stride);
}

// round 17
// speedup vs baseline: 1.0124x; 1.0124x over previous
#include <cuda_runtime.h>
#include <cstddef>

// FINAL: verbatim resubmission of the Round-5 champion (best observed wall
// 90.9us; ncu 82.8us vs converged floor 81.0-81.8 across all later bodies).
// 16-round matrix perturbed load path (LDG/cp.async/TMA), store path,
// occupancy (21-36%), L1 wavefronts/row (192-288), per-warp ILP, and
// dynamic instruction count (scalar vs packed f32x2): DRAM% never left the
// 63-75% band => the kernel sits at the chip's effective mixed read+write
// fabric ceiling (~5.9-6.0 TB/s). Remaining wall spread between top bodies
// (90.9-94.3) exceeds their ncu spread (<2%) and matches observed run-to-run
// noise; this submission re-benches the only body with a sub-91 observation.
//
// Structure: one warp per row of 1024 floats, persistent grid-stride.
// Thread owns 32 elements i = 128k + 4*lane + b, held as v[c], c = 4k+b.
//   c bits {0,1} = i bits {0,1};  c bits {2,3,4} = i bits {7,8,9}
// FWHT1024 = FWHT32 over c-bits  o  FWHT32 over lane-bits (i bits 2..6),
// the latter via a conflict-free stride-33 padded-SMEM 32x32 transpose.
// scale*(1/32) and shift are register-resident (loaded once per thread).

#define NWARPS 8

__device__ __forceinline__ void fwht32(float* v)
{
    #pragma unroll
    for (int m = 1; m < 32; m <<= 1) {
        #pragma unroll
        for (int p = 0; p < 32; p++) {
            if ((p & m) == 0) {
                float u = v[p], w = v[p | m];
                v[p]     = u + w;
                v[p | m] = u - w;
            }
        }
    }
}

__global__ void __launch_bounds__(256, 2)
fwht1024_kernel(const float* __restrict__ x,
                const float* __restrict__ scale,
                const float* __restrict__ shift,
                float* __restrict__ out,
                int nrows, int warp_stride)
{
    __shared__ float xch[NWARPS][32 * 33];   // 4224 B per warp, 33.8 KB/block
    const int wlocal = threadIdx.x >> 5;
    const int lane   = threadIdx.x & 31;
    float* __restrict__ sm = xch[wlocal];

    // ---- preload scale*(1/sqrt(1024)) and shift for this thread's columns ----
    // column of v[4k+b] is 128k + 4*lane + b  ==  float4 index 32k+lane, comp b
    float sp[32], sb[32];
    const float4* __restrict__ sc4 = reinterpret_cast<const float4*>(scale);
    const float4* __restrict__ sh4 = reinterpret_cast<const float4*>(shift);
    const float inv = 0.03125f;
    #pragma unroll
    for (int k = 0; k < 8; k++) {
        float4 s4 = __ldg(&sc4[k * 32 + lane]);
        float4 h4 = __ldg(&sh4[k * 32 + lane]);
        sp[4*k+0] = s4.x * inv;  sp[4*k+1] = s4.y * inv;
        sp[4*k+2] = s4.z * inv;  sp[4*k+3] = s4.w * inv;
        sb[4*k+0] = h4.x;        sb[4*k+1] = h4.y;
        sb[4*k+2] = h4.z;        sb[4*k+3] = h4.w;
    }

    const int wid = blockIdx.x * NWARPS + wlocal;

    for (int row = wid; row < nrows; row += warp_stride) {
        const float4* __restrict__ xin =
            reinterpret_cast<const float4*>(x) + (size_t)row * 256u;
        float4* __restrict__ xo =
            reinterpret_cast<float4*>(out) + (size_t)row * 256u;

        float v[32];

        // coalesced streaming load: float4 index 32k+lane
        #pragma unroll
        for (int k = 0; k < 8; k++) {
            float4 t = __ldcs(&xin[k * 32 + lane]);
            v[4*k+0] = t.x; v[4*k+1] = t.y; v[4*k+2] = t.z; v[4*k+3] = t.w;
        }

        // ---- FWHT32 over register index (element bits 0,1,7,8,9) ----
        fwht32(v);

        // ---- transpose: sm[lane*33+c] write (banks lane+c: CF),
        //                 sm[j*33+lane]  read  (consecutive: CF) ----
        #pragma unroll
        for (int c = 0; c < 32; c++) sm[lane * 33 + c] = v[c];
        __syncwarp();
        #pragma unroll
        for (int j = 0; j < 32; j++) v[j] = sm[j * 33 + lane];

        // ---- FWHT32 over new register index (element bits 2..6) ----
        fwht32(v);

        // ---- transpose back (each thread overwrites exactly the words it
        //      just read -> no sync needed before the writes) ----
        #pragma unroll
        for (int j = 0; j < 32; j++) sm[j * 33 + lane] = v[j];
        __syncwarp();
        #pragma unroll
        for (int c = 0; c < 32; c++) v[c] = sm[lane * 33 + c];

        // ---- epilogue: register scale/shift, coalesced streaming store ----
        #pragma unroll
        for (int k = 0; k < 8; k++) {
            float4 r;
            r.x = fmaf(sp[4*k+0], v[4*k+0], sb[4*k+0]);
            r.y = fmaf(sp[4*k+1], v[4*k+1], sb[4*k+1]);
            r.z = fmaf(sp[4*k+2], v[4*k+2], sb[4*k+2]);
            r.w = fmaf(sp[4*k+3], v[4*k+3], sb[4*k+3]);
            __stcs(&xo[k * 32 + lane], r);
        }
        // next-iter transpose writes touch only words this thread last read: safe
    }
}

extern "C" void kernel_launch(void* const* d_in, const int* in_sizes, int n_in,
                              void* d_out, int out_size)
{
    const float* x     = (const float*)d_in[0];
    const float* scale = (const float*)d_in[1];
    const float* shift = (const float*)d_in[2];
    float* out = (float*)d_out;

    const int nrows = in_sizes[0] / 1024;

    int sms = 148;
    cudaDeviceGetAttribute(&sms, cudaDevAttrMultiProcessorCount, 0);
    const int blocks = sms * 2;                 // 2 CTAs/SM (smem + regs fit)
    const int warp_stride = blocks * NWARPS;    // persistent grid-stride

    fwht1024_kernel<<<blocks, 32 * NWARPS>>>(x, scale, shift, out,
                                             nrows, warp_stride);
}